// round 1
// baseline (speedup 1.0000x reference)
#include <cuda_runtime.h>

// ---------------------------------------------------------------------------
// AdaConv2d: instance-norm -> per-sample adaptive grouped 3x3 (+fused 1x1+bias)
//            -> static 3x3 conv 256->256, reflect padding everywhere.
// Round 0: fp32 baseline. K3 (final conv) is the 154.6 GF hot spot.
// ---------------------------------------------------------------------------

constexpr int B   = 8;
constexpr int C   = 256;
constexpr int H   = 128;
constexpr int W   = 128;
constexpr int G   = 32;
constexpr int CPG = 8;      // channels per group
constexpr int OUT = 256;
constexpr int HW  = H * W;
constexpr float EPS = 1e-5f;

// Scratch (no cudaMalloc allowed): intermediate y [B,C,H,W] + per-(b,c) stats.
static __device__ float g_mean[B * C];
static __device__ float g_rsig[B * C];
static __device__ float g_y[(size_t)B * C * H * W];

__device__ __forceinline__ int reflect_idx(int v, int n) {
    v = v < 0 ? -v : v;
    v = v >= n ? 2 * n - 2 - v : v;
    return v;
}

// ---------------------------------------------------------------------------
// K1: per-(b,c) mean / rsqrt(var+eps).  One block per (b,c), float4 loads.
// ---------------------------------------------------------------------------
__global__ void stats_kernel(const float* __restrict__ x) {
    int bc = blockIdx.x;
    const float4* xp = reinterpret_cast<const float4*>(x + (size_t)bc * HW);
    float s = 0.f, ss = 0.f;
    #pragma unroll 4
    for (int i = threadIdx.x; i < HW / 4; i += 256) {
        float4 v = xp[i];
        s  += (v.x + v.y) + (v.z + v.w);
        ss += v.x * v.x + v.y * v.y + v.z * v.z + v.w * v.w;
    }
    #pragma unroll
    for (int o = 16; o; o >>= 1) {
        s  += __shfl_down_sync(0xFFFFFFFFu, s, o);
        ss += __shfl_down_sync(0xFFFFFFFFu, ss, o);
    }
    __shared__ float sh_s[8], sh_ss[8];
    int wid = threadIdx.x >> 5, lid = threadIdx.x & 31;
    if (lid == 0) { sh_s[wid] = s; sh_ss[wid] = ss; }
    __syncthreads();
    if (threadIdx.x == 0) {
        float ts = 0.f, tss = 0.f;
        #pragma unroll
        for (int i = 0; i < 8; i++) { ts += sh_s[i]; tss += sh_ss[i]; }
        float m   = ts * (1.f / HW);
        float var = tss * (1.f / HW) - m * m;
        g_mean[bc] = m;
        g_rsig[bc] = rsqrtf(var + EPS);
    }
}

// ---------------------------------------------------------------------------
// K2: fused normalize + adaptive grouped 3x3 + grouped 1x1 + bias.
// Fold the 1x1 into the spatial weights:  W_eff[o][j][k] = sum_i wp[o,i]*ws[i,j,k]
// Block = one (b, g) group x 32x16 spatial tile. Writes g_y.
// ---------------------------------------------------------------------------
constexpr int T2W = 32, T2H = 16;

__global__ void ada_kernel(const float* __restrict__ x,
                           const float* __restrict__ ws,
                           const float* __restrict__ wp,
                           const float* __restrict__ bias) {
    __shared__ float s_in[CPG][T2H + 2][35];   // padded stride 35 (conflict-free)
    __shared__ float s_weff[CPG][CPG][9];      // [o][j][k]
    __shared__ float s_wp[CPG][CPG];           // [o][i]

    int bg = blockIdx.z;
    int b = bg / G, g = bg % G;
    int x0 = blockIdx.x * T2W, y0 = blockIdx.y * T2H;
    int tid = threadIdx.x;

    if (tid < CPG * CPG) {
        int o = tid >> 3, i = tid & 7;
        s_wp[o][i] = wp[(b * C + g * CPG + o) * CPG + i];
    }
    __syncthreads();

    // Effective weights: 576 entries, each a dot over 8.
    for (int t = tid; t < CPG * CPG * 9; t += 256) {
        int o = t / 72, r = t % 72, j = r / 9, k = r % 9;
        float acc = 0.f;
        #pragma unroll
        for (int i = 0; i < CPG; i++)
            acc += s_wp[o][i] * ws[((b * C + g * CPG + i) * CPG + j) * 9 + k];
        s_weff[o][j][k] = acc;
    }

    // Normalized input tile with reflect halo (8 ch x 18 x 34).
    for (int e = tid; e < CPG * (T2H + 2) * 34; e += 256) {
        int j   = e / ((T2H + 2) * 34);
        int r   = (e / 34) % (T2H + 2);
        int col = e % 34;
        int gy = reflect_idx(y0 + r - 1, H);
        int gx = reflect_idx(x0 + col - 1, W);
        int cg = b * C + g * CPG + j;
        s_in[j][r][col] = (x[(size_t)cg * HW + gy * W + gx] - g_mean[cg]) * g_rsig[cg];
    }
    __syncthreads();

    // Each thread: 2 adjacent x-pixels, all 8 output channels of the group.
    int px = (tid & 15) * 2;   // 0..30
    int py = tid >> 4;         // 0..15
    float acc[CPG][2];
    #pragma unroll
    for (int o = 0; o < CPG; o++) { acc[o][0] = 0.f; acc[o][1] = 0.f; }

    #pragma unroll
    for (int j = 0; j < CPG; j++) {
        #pragma unroll
        for (int ky = 0; ky < 3; ky++) {
            float i0 = s_in[j][py + ky][px + 0];
            float i1 = s_in[j][py + ky][px + 1];
            float i2 = s_in[j][py + ky][px + 2];
            float i3 = s_in[j][py + ky][px + 3];
            #pragma unroll
            for (int o = 0; o < CPG; o++) {
                float w0 = s_weff[o][j][ky * 3 + 0];
                float w1 = s_weff[o][j][ky * 3 + 1];
                float w2 = s_weff[o][j][ky * 3 + 2];
                acc[o][0] += w0 * i0 + w1 * i1 + w2 * i2;
                acc[o][1] += w0 * i1 + w1 * i2 + w2 * i3;
            }
        }
    }

    #pragma unroll
    for (int o = 0; o < CPG; o++) {
        int cg = b * C + g * CPG + o;
        float bz = bias[cg];
        int base = cg * HW + (y0 + py) * W + (x0 + px);
        g_y[base]     = acc[o][0] + bz;
        g_y[base + 1] = acc[o][1] + bz;
    }
}

// ---------------------------------------------------------------------------
// K3: static 3x3 conv 256->256 with reflect pad (the 154.6 GF hot spot).
// Implicit-GEMM-style direct conv, fp32. Block: 64 oc x (32w x 8h) tile.
// Thread: 8 oc x 8 consecutive x-pixels = 64 accumulators.
// Input channels processed in chunks of 4 through smem.
// Output staged through padded smem for coalesced stores.
// ---------------------------------------------------------------------------
constexpr int T3W = 32, T3H = 8, OCT = 64, CCH = 4;

__global__ __launch_bounds__(256)
void final_conv_kernel(const float* __restrict__ cw,
                       const float* __restrict__ cb,
                       float* __restrict__ out) {
    __shared__ float s_in[CCH][T3H + 2][35];   // 4 ch x 10 x 34 (stride 35)
    __shared__ float s_w[CCH][OCT][9];         // 4 ch x 64 oc x 9
    __shared__ float s_stage[8][T3H][33];      // coalescing stage (stride 33)

    int bz  = blockIdx.z;           // b*4 + oct
    int b   = bz >> 2, oct = bz & 3;
    int x0  = blockIdx.x * T3W, y0 = blockIdx.y * T3H;
    int tid = threadIdx.x;
    int xg  = tid & 3;              // x block: pixels xg*8 .. xg*8+7
    int row = (tid >> 2) & 7;       // 0..7
    int ocg = tid >> 5;             // 0..7 -> oc = oct*64 + ocg*8 + o

    float acc[8][8];
    #pragma unroll
    for (int o = 0; o < 8; o++)
        #pragma unroll
        for (int i = 0; i < 8; i++)
            acc[o][i] = 0.f;

    for (int c0 = 0; c0 < C; c0 += CCH) {
        // input tile (reflect halo) for 4 channels: 4*10*34 = 1360 elems
        for (int e = tid; e < CCH * (T3H + 2) * 34; e += 256) {
            int cc  = e / ((T3H + 2) * 34);
            int r   = (e / 34) % (T3H + 2);
            int col = e % 34;
            int gy = reflect_idx(y0 + r - 1, H);
            int gx = reflect_idx(x0 + col - 1, W);
            s_in[cc][r][col] = g_y[((b * C + c0 + cc) * H + gy) * W + gx];
        }
        // weights for 64 oc x 4 ch: 2304 elems
        for (int e = tid; e < CCH * OCT * 9; e += 256) {
            int cc   = e / (OCT * 9);
            int r    = e % (OCT * 9);
            int oc_l = r / 9;
            int k    = r % 9;
            s_w[cc][oc_l][k] = cw[((oct * OCT + oc_l) * C + c0 + cc) * 9 + k];
        }
        __syncthreads();

        #pragma unroll
        for (int cc = 0; cc < CCH; cc++) {
            #pragma unroll
            for (int ky = 0; ky < 3; ky++) {
                float in[10];
                #pragma unroll
                for (int i = 0; i < 10; i++)
                    in[i] = s_in[cc][row + ky][xg * 8 + i];
                #pragma unroll
                for (int kx = 0; kx < 3; kx++) {
                    #pragma unroll
                    for (int o = 0; o < 8; o++) {
                        float w = s_w[cc][ocg * 8 + o][ky * 3 + kx];
                        #pragma unroll
                        for (int i = 0; i < 8; i++)
                            acc[o][i] += w * in[kx + i];
                    }
                }
            }
        }
        __syncthreads();
    }

    // Epilogue: add conv bias, stage through smem, coalesced global stores.
    float cbv[8];
    #pragma unroll
    for (int o = 0; o < 8; o++)
        cbv[o] = cb[oct * OCT + ocg * 8 + o];

    for (int step = 0; step < 8; step++) {
        #pragma unroll
        for (int i = 0; i < 8; i++)
            s_stage[ocg][row][xg * 8 + i] = acc[step][i] + cbv[step];
        __syncthreads();
        for (int k = tid; k < 8 * T3H * T3W; k += 256) {
            int p   = k >> 8;          // oc plane (= ocg of producer)
            int idx = k & 255;
            int rr  = idx >> 5;
            int xx  = idx & 31;
            int oc  = oct * OCT + p * 8 + step;
            out[((b * OUT + oc) * H + (y0 + rr)) * W + (x0 + xx)] = s_stage[p][rr][xx];
        }
        __syncthreads();
    }
}

// ---------------------------------------------------------------------------
extern "C" void kernel_launch(void* const* d_in, const int* in_sizes, int n_in,
                              void* d_out, int out_size) {
    const float* x    = (const float*)d_in[0];
    const float* ws   = (const float*)d_in[1];
    const float* wp   = (const float*)d_in[2];
    const float* bias = (const float*)d_in[3];
    const float* cw   = (const float*)d_in[4];
    const float* cb   = (const float*)d_in[5];
    float* out = (float*)d_out;

    stats_kernel<<<B * C, 256>>>(x);
    ada_kernel<<<dim3(W / T2W, H / T2H, B * G), 256>>>(x, ws, wp, bias);
    final_conv_kernel<<<dim3(W / T3W, H / T3H, B * 4), 256>>>(cw, cb, out);
}

// round 4
// speedup vs baseline: 2.8646x; 2.8646x over previous
#include <cuda_runtime.h>
#include <cuda_bf16.h>
#include <cstdint>

// ---------------------------------------------------------------------------
// AdaConv2d on GB300 (plain sm_103 target -> no tcgen05; mma.sync/HMMA path):
//   K1 stats -> K2 instancenorm + adaptive grouped conv (bf16 hi/lo NHWC,
//   reflect-pre-padded) -> halo -> weight prepack -> K3 mma.sync implicit-GEMM
//   final 3x3 conv (9 tap-GEMMs, bf16 hi/lo 3-term split, fp32 accum).
// R4 fix: B operand uses NON-trans ldmatrix (smem [pixel][ci] is already
// col-major for mma.row.col; .trans scrambled the fragment).
// ---------------------------------------------------------------------------

constexpr int B   = 8;
constexpr int C   = 256;
constexpr int H   = 128;
constexpr int W   = 128;
constexpr int G   = 32;
constexpr int CPG = 8;
constexpr int OUT = 256;
constexpr int HW  = H * W;
constexpr float EPS = 1e-5f;

constexpr int HP = H + 2;
constexpr int WP = W + 2;

constexpr int MTILE  = 128;   // oc per CTA
constexpr int CCH    = 64;    // ci per smem stage

// Device scratch
static __device__ float g_mean[B * C];
static __device__ float g_rsig[B * C];
static __device__ __nv_bfloat16 g_yhi[(size_t)B * HP * WP * C];   // NHWC padded
static __device__ __nv_bfloat16 g_ylo[(size_t)B * HP * WP * C];
static __device__ __nv_bfloat16 g_whi[9 * OUT * C];               // [tap][oc][ci]
static __device__ __nv_bfloat16 g_wlo[9 * OUT * C];

__device__ __forceinline__ int reflect_idx(int v, int n) {
    v = v < 0 ? -v : v;
    v = v >= n ? 2 * n - 2 - v : v;
    return v;
}

#define SWZ128(off) ((off) ^ (((off) >> 3) & 0x70))

__device__ __forceinline__ uint32_t smem_u32(const void* p) {
    uint32_t a;
    asm("{ .reg .u64 t; cvta.to.shared.u64 t, %1; cvt.u32.u64 %0, t; }"
        : "=r"(a) : "l"(p));
    return a;
}
__device__ __forceinline__ void ldmx4(uint32_t* r, uint32_t addr) {
    asm volatile("ldmatrix.sync.aligned.m8n8.x4.shared.b16 {%0,%1,%2,%3}, [%4];"
                 : "=r"(r[0]), "=r"(r[1]), "=r"(r[2]), "=r"(r[3]) : "r"(addr));
}
__device__ __forceinline__ void mma16816(float* d, const uint32_t* a,
                                         const uint32_t* b) {
    asm volatile(
        "mma.sync.aligned.m16n8k16.row.col.f32.bf16.bf16.f32 "
        "{%0,%1,%2,%3},{%4,%5,%6,%7},{%8,%9},{%0,%1,%2,%3};"
        : "+f"(d[0]), "+f"(d[1]), "+f"(d[2]), "+f"(d[3])
        : "r"(a[0]), "r"(a[1]), "r"(a[2]), "r"(a[3]), "r"(b[0]), "r"(b[1]));
}

// ---------------------------------------------------------------------------
// K1: per-(b,c) mean / rsqrt(var+eps)
// ---------------------------------------------------------------------------
__global__ void stats_kernel(const float* __restrict__ x) {
    int bc = blockIdx.x;
    const float4* xp = reinterpret_cast<const float4*>(x + (size_t)bc * HW);
    float s = 0.f, ss = 0.f;
    #pragma unroll 4
    for (int i = threadIdx.x; i < HW / 4; i += 256) {
        float4 v = xp[i];
        s  += (v.x + v.y) + (v.z + v.w);
        ss += v.x * v.x + v.y * v.y + v.z * v.z + v.w * v.w;
    }
    #pragma unroll
    for (int o = 16; o; o >>= 1) {
        s  += __shfl_down_sync(0xFFFFFFFFu, s, o);
        ss += __shfl_down_sync(0xFFFFFFFFu, ss, o);
    }
    __shared__ float sh_s[8], sh_ss[8];
    int wid = threadIdx.x >> 5, lid = threadIdx.x & 31;
    if (lid == 0) { sh_s[wid] = s; sh_ss[wid] = ss; }
    __syncthreads();
    if (threadIdx.x == 0) {
        float ts = 0.f, tss = 0.f;
        #pragma unroll
        for (int i = 0; i < 8; i++) { ts += sh_s[i]; tss += sh_ss[i]; }
        float m   = ts * (1.f / HW);
        float var = tss * (1.f / HW) - m * m;
        g_mean[bc] = m;
        g_rsig[bc] = rsqrtf(var + EPS);
    }
}

// ---------------------------------------------------------------------------
// Weight prepack: conv_w [OUT][C][3][3] fp32 -> [tap][oc][ci] bf16 hi/lo
// ---------------------------------------------------------------------------
__global__ void prepack_kernel(const float* __restrict__ cw) {
    int idx = blockIdx.x * 256 + threadIdx.x;
    int tap = idx >> 16;
    int r   = idx & 0xFFFF;
    int oc  = r >> 8, ci = r & 255;
    float v = cw[(oc * C + ci) * 9 + tap];
    __nv_bfloat16 h = __float2bfloat16(v);
    g_whi[idx] = h;
    g_wlo[idx] = __float2bfloat16(v - __bfloat162float(h));
}

// ---------------------------------------------------------------------------
// K2: normalize + adaptive grouped 3x3 + 1x1 + bias -> bf16 hi/lo NHWC padded
// ---------------------------------------------------------------------------
constexpr int T2W = 32, T2H = 16;

__global__ void ada_kernel(const float* __restrict__ x,
                           const float* __restrict__ ws,
                           const float* __restrict__ wp,
                           const float* __restrict__ bias) {
    __shared__ float s_in[CPG][T2H + 2][35];
    __shared__ float s_weff[CPG][CPG][9];
    __shared__ float s_wp[CPG][CPG];

    int bg = blockIdx.z;
    int b = bg / G, g = bg % G;
    int x0 = blockIdx.x * T2W, y0 = blockIdx.y * T2H;
    int tid = threadIdx.x;

    if (tid < CPG * CPG) {
        int o = tid >> 3, i = tid & 7;
        s_wp[o][i] = wp[(b * C + g * CPG + o) * CPG + i];
    }
    __syncthreads();

    for (int t = tid; t < CPG * CPG * 9; t += 256) {
        int o = t / 72, r = t % 72, j = r / 9, k = r % 9;
        float acc = 0.f;
        #pragma unroll
        for (int i = 0; i < CPG; i++)
            acc += s_wp[o][i] * ws[((b * C + g * CPG + i) * CPG + j) * 9 + k];
        s_weff[o][j][k] = acc;
    }

    for (int e = tid; e < CPG * (T2H + 2) * 34; e += 256) {
        int j   = e / ((T2H + 2) * 34);
        int r   = (e / 34) % (T2H + 2);
        int col = e % 34;
        int gy = reflect_idx(y0 + r - 1, H);
        int gx = reflect_idx(x0 + col - 1, W);
        int cg = b * C + g * CPG + j;
        s_in[j][r][col] = (x[(size_t)cg * HW + gy * W + gx] - g_mean[cg]) * g_rsig[cg];
    }
    __syncthreads();

    int px = (tid & 15) * 2;
    int py = tid >> 4;
    float acc[CPG][2];
    #pragma unroll
    for (int o = 0; o < CPG; o++) { acc[o][0] = 0.f; acc[o][1] = 0.f; }

    #pragma unroll
    for (int j = 0; j < CPG; j++) {
        #pragma unroll
        for (int ky = 0; ky < 3; ky++) {
            float i0 = s_in[j][py + ky][px + 0];
            float i1 = s_in[j][py + ky][px + 1];
            float i2 = s_in[j][py + ky][px + 2];
            float i3 = s_in[j][py + ky][px + 3];
            #pragma unroll
            for (int o = 0; o < CPG; o++) {
                float w0 = s_weff[o][j][ky * 3 + 0];
                float w1 = s_weff[o][j][ky * 3 + 1];
                float w2 = s_weff[o][j][ky * 3 + 2];
                acc[o][0] += w0 * i0 + w1 * i1 + w2 * i2;
                acc[o][1] += w0 * i1 + w1 * i2 + w2 * i3;
            }
        }
    }

    union U16 { __nv_bfloat16 h[8]; uint4 u; };
    U16 uh0, ul0, uh1, ul1;
    #pragma unroll
    for (int o = 0; o < CPG; o++) {
        float bz = bias[b * C + g * CPG + o];
        float v0 = acc[o][0] + bz;
        float v1 = acc[o][1] + bz;
        __nv_bfloat16 h0 = __float2bfloat16(v0);
        __nv_bfloat16 h1 = __float2bfloat16(v1);
        uh0.h[o] = h0; ul0.h[o] = __float2bfloat16(v0 - __bfloat162float(h0));
        uh1.h[o] = h1; ul1.h[o] = __float2bfloat16(v1 - __bfloat162float(h1));
    }
    size_t pbase = ((size_t)(b * HP + (y0 + py + 1)) * WP + (x0 + px + 1)) * C + g * CPG;
    *reinterpret_cast<uint4*>(g_yhi + pbase)     = uh0.u;
    *reinterpret_cast<uint4*>(g_ylo + pbase)     = ul0.u;
    *reinterpret_cast<uint4*>(g_yhi + pbase + C) = uh1.u;
    *reinterpret_cast<uint4*>(g_ylo + pbase + C) = ul1.u;
}

// ---------------------------------------------------------------------------
// Halo fill (reflect) for the padded NHWC planes
// ---------------------------------------------------------------------------
__global__ void halo_kernel() {
    int e = blockIdx.x;      // 0..515
    int b = blockIdx.y;
    int py, px;
    if (e < 130)       { py = 0;            px = e; }
    else if (e < 260)  { py = 129;          px = e - 130; }
    else if (e < 388)  { py = e - 260 + 1;  px = 0; }
    else               { py = e - 388 + 1;  px = 129; }
    int sy = reflect_idx(py - 1, H) + 1;
    int sx = reflect_idx(px - 1, W) + 1;
    size_t dst = ((size_t)(b * HP + py) * WP + px) * C + threadIdx.x;
    size_t src = ((size_t)(b * HP + sy) * WP + sx) * C + threadIdx.x;
    g_yhi[dst] = g_yhi[src];
    g_ylo[dst] = g_ylo[src];
}

// ---------------------------------------------------------------------------
// K3: mma.sync implicit-GEMM final conv.
// CTA: 128 oc x 128 px (one row). 8 warps (2M x 4N), warp tile 64x32.
// B smem tile holds 130 px rows x 64 ci so all 3 dx taps reuse one load.
// B is [pixel][ci] (k-contiguous) == col-major for mma.row.col -> NON-trans
// ldmatrix; 4-matrix grouping: lanes 0-7 (n,k0), 8-15 (n,k8),
// 16-23 (n+8,k0), 24-31 (n+8,k8) -> regs (r0,r1) n-block0, (r2,r3) n-block1.
// ---------------------------------------------------------------------------
constexpr int OFF_A_HI = 0;
constexpr int OFF_A_LO = OFF_A_HI + MTILE * 128;        // 16384
constexpr int OFF_B_HI = OFF_A_LO + MTILE * 128;        // 32768
constexpr int OFF_B_LO = OFF_B_HI + 130 * 128;          // 49408
constexpr int SMEM_K3  = OFF_B_LO + 130 * 128;          // 66048

__global__ __launch_bounds__(256, 2)
void final_mma_kernel(const float* __restrict__ cb, float* __restrict__ out) {
    extern __shared__ char sb[];
    uint32_t su = smem_u32(sb);
    int tid  = threadIdx.x;
    int warp = tid >> 5, lane = tid & 31;
    int wm = warp >> 2;          // 0..1  -> oc base wm*64
    int wn = warp & 3;           // 0..3  -> px base wn*32

    int y0  = blockIdx.x;        // output row
    int b   = blockIdx.y;
    int ocb = blockIdx.z;        // oc block of 128

    float acc[4][4][4];
    #pragma unroll
    for (int mi = 0; mi < 4; mi++)
        #pragma unroll
        for (int ni = 0; ni < 4; ni++)
            #pragma unroll
            for (int q = 0; q < 4; q++)
                acc[mi][ni][q] = 0.f;

    // A: lanes 0-7 rows0-7 k0 | 8-15 rows8-15 k0 | 16-23 rows0-7 k8 | 24-31 rows8-15 k8
    uint32_t a_row  = (uint32_t)(wm * 64 + (lane & 15));
    uint32_t a_kh   = (uint32_t)(lane >> 4) * 16;
    // B: lanes 0-7 n0-7 k0 | 8-15 n0-7 k8 | 16-23 n8-15 k0 | 24-31 n8-15 k8
    uint32_t b_row  = (uint32_t)(wn * 32 + (lane & 7) + ((lane >> 4) << 3));
    uint32_t b_kh   = (uint32_t)((lane >> 3) & 1) * 16;

    for (int c0 = 0; c0 < C; c0 += CCH) {
        for (int dyi = 0; dyi < 3; dyi++) {
            for (int dxi = 0; dxi < 3; dxi++) {
                __syncthreads();   // previous mma done before overwrite
                if (dxi == 0) {
                    // B tile: 130 px rows x 64 ci (hi+lo)
                    for (int e = tid; e < 130 * 8; e += 256) {
                        int r = e >> 3, j = e & 7;
                        size_t gi = ((size_t)(b * HP + y0 + dyi) * WP + r) * C
                                    + c0 + j * 8;
                        uint4 vh = *reinterpret_cast<const uint4*>(g_yhi + gi);
                        uint4 vl = *reinterpret_cast<const uint4*>(g_ylo + gi);
                        uint32_t off = SWZ128((uint32_t)(r * 128 + j * 16));
                        *reinterpret_cast<uint4*>(sb + OFF_B_HI + off) = vh;
                        *reinterpret_cast<uint4*>(sb + OFF_B_LO + off) = vl;
                    }
                }
                // A tile: 128 oc x 64 ci (hi+lo) for tap
                int tap = dyi * 3 + dxi;
                #pragma unroll
                for (int e = tid; e < MTILE * 8; e += 256) {
                    int r = e >> 3, j = e & 7;
                    size_t gi = ((size_t)(tap * OUT + ocb * MTILE + r)) * C
                                + c0 + j * 8;
                    uint4 vh = *reinterpret_cast<const uint4*>(g_whi + gi);
                    uint4 vl = *reinterpret_cast<const uint4*>(g_wlo + gi);
                    uint32_t off = SWZ128((uint32_t)(r * 128 + j * 16));
                    *reinterpret_cast<uint4*>(sb + OFF_A_HI + off) = vh;
                    *reinterpret_cast<uint4*>(sb + OFF_A_LO + off) = vl;
                }
                __syncthreads();

                #pragma unroll
                for (int ks = 0; ks < 4; ks++) {
                    uint32_t kb = (uint32_t)ks * 32;
                    uint32_t aH[4][4], aL[4][4], bH[2][4], bL[2][4];
                    #pragma unroll
                    for (int mi = 0; mi < 4; mi++) {
                        uint32_t off = SWZ128((a_row + mi * 16) * 128 + kb + a_kh);
                        ldmx4(aH[mi], su + OFF_A_HI + off);
                        ldmx4(aL[mi], su + OFF_A_LO + off);
                    }
                    #pragma unroll
                    for (int nh = 0; nh < 2; nh++) {
                        uint32_t off = SWZ128((b_row + nh * 16 + dxi) * 128 + kb + b_kh);
                        ldmx4(bH[nh], su + OFF_B_HI + off);
                        ldmx4(bL[nh], su + OFF_B_LO + off);
                    }
                    #pragma unroll
                    for (int mi = 0; mi < 4; mi++)
                        #pragma unroll
                        for (int ni = 0; ni < 4; ni++) {
                            const uint32_t* bh = &bH[ni >> 1][(ni & 1) * 2];
                            const uint32_t* bl = &bL[ni >> 1][(ni & 1) * 2];
                            mma16816(acc[mi][ni], aH[mi], bh);
                            mma16816(acc[mi][ni], aL[mi], bh);
                            mma16816(acc[mi][ni], aH[mi], bl);
                        }
                }
            }
        }
    }

    // Epilogue: +bias, direct float2 stores
    int row0 = lane >> 2;
    int col2 = (lane & 3) * 2;
    #pragma unroll
    for (int mi = 0; mi < 4; mi++) {
        int oc = ocb * MTILE + wm * 64 + mi * 16 + row0;
        float bz0 = cb[oc];
        float bz1 = cb[oc + 8];
        size_t base0 = (((size_t)(b * OUT + oc))     * H + y0) * W;
        size_t base1 = (((size_t)(b * OUT + oc + 8)) * H + y0) * W;
        #pragma unroll
        for (int ni = 0; ni < 4; ni++) {
            int px = wn * 32 + ni * 8 + col2;
            float2 v0 = { acc[mi][ni][0] + bz0, acc[mi][ni][1] + bz0 };
            float2 v1 = { acc[mi][ni][2] + bz1, acc[mi][ni][3] + bz1 };
            *reinterpret_cast<float2*>(out + base0 + px) = v0;
            *reinterpret_cast<float2*>(out + base1 + px) = v1;
        }
    }
}

// ---------------------------------------------------------------------------
extern "C" void kernel_launch(void* const* d_in, const int* in_sizes, int n_in,
                              void* d_out, int out_size) {
    const float* x    = (const float*)d_in[0];
    const float* ws   = (const float*)d_in[1];
    const float* wp   = (const float*)d_in[2];
    const float* bias = (const float*)d_in[3];
    const float* cw   = (const float*)d_in[4];
    const float* cb   = (const float*)d_in[5];
    float* out = (float*)d_out;

    cudaFuncSetAttribute(final_mma_kernel,
                         cudaFuncAttributeMaxDynamicSharedMemorySize, SMEM_K3);

    stats_kernel<<<B * C, 256>>>(x);
    prepack_kernel<<<9 * OUT * C / 256, 256>>>(cw);
    ada_kernel<<<dim3(W / T2W, H / T2H, B * G), 256>>>(x, ws, wp, bias);
    halo_kernel<<<dim3(516, B), 256>>>();
    final_mma_kernel<<<dim3(H, B, OUT / MTILE), 256, SMEM_K3>>>(cb, out);
}

// round 5
// speedup vs baseline: 3.1517x; 1.1002x over previous
#include <cuda_runtime.h>
#include <cuda_bf16.h>
#include <cstdint>

// ---------------------------------------------------------------------------
// AdaConv2d on GB300 (plain sm_103 target -> no tcgen05; mma.sync/HMMA path):
//   K1 stats -> K2 instancenorm + adaptive grouped conv (bf16 hi/lo NHWC,
//   reflect-pre-padded) -> halo -> weight prepack -> K3 mma.sync implicit-GEMM
//   final 3x3 conv (9 tap-GEMMs, bf16 hi/lo 3-term split, fp32 accum).
// R5: K3 mainloop pipelined with cp.async + double-buffered A tile,
//     one barrier per iteration (was 2 + register-roundtrip staging).
// ---------------------------------------------------------------------------

constexpr int B   = 8;
constexpr int C   = 256;
constexpr int H   = 128;
constexpr int W   = 128;
constexpr int G   = 32;
constexpr int CPG = 8;
constexpr int OUT = 256;
constexpr int HW  = H * W;
constexpr float EPS = 1e-5f;

constexpr int HP = H + 2;
constexpr int WP = W + 2;

constexpr int MTILE = 128;   // oc per CTA
constexpr int CCH   = 64;    // ci per smem stage

// Device scratch
static __device__ float g_mean[B * C];
static __device__ float g_rsig[B * C];
static __device__ __nv_bfloat16 g_yhi[(size_t)B * HP * WP * C];   // NHWC padded
static __device__ __nv_bfloat16 g_ylo[(size_t)B * HP * WP * C];
static __device__ __nv_bfloat16 g_whi[9 * OUT * C];               // [tap][oc][ci]
static __device__ __nv_bfloat16 g_wlo[9 * OUT * C];

__device__ __forceinline__ int reflect_idx(int v, int n) {
    v = v < 0 ? -v : v;
    v = v >= n ? 2 * n - 2 - v : v;
    return v;
}

#define SWZ128(off) ((off) ^ (((off) >> 3) & 0x70))

__device__ __forceinline__ uint32_t smem_u32(const void* p) {
    uint32_t a;
    asm("{ .reg .u64 t; cvta.to.shared.u64 t, %1; cvt.u32.u64 %0, t; }"
        : "=r"(a) : "l"(p));
    return a;
}
__device__ __forceinline__ void cpa16(uint32_t dst, const void* src) {
    asm volatile("cp.async.cg.shared.global [%0], [%1], 16;"
                 :: "r"(dst), "l"(src));
}
#define CP_COMMIT() asm volatile("cp.async.commit_group;" ::: "memory")
#define CP_WAIT0()  asm volatile("cp.async.wait_group 0;" ::: "memory")

__device__ __forceinline__ void ldmx4(uint32_t* r, uint32_t addr) {
    asm volatile("ldmatrix.sync.aligned.m8n8.x4.shared.b16 {%0,%1,%2,%3}, [%4];"
                 : "=r"(r[0]), "=r"(r[1]), "=r"(r[2]), "=r"(r[3]) : "r"(addr));
}
__device__ __forceinline__ void mma16816(float* d, const uint32_t* a,
                                         const uint32_t* b) {
    asm volatile(
        "mma.sync.aligned.m16n8k16.row.col.f32.bf16.bf16.f32 "
        "{%0,%1,%2,%3},{%4,%5,%6,%7},{%8,%9},{%0,%1,%2,%3};"
        : "+f"(d[0]), "+f"(d[1]), "+f"(d[2]), "+f"(d[3])
        : "r"(a[0]), "r"(a[1]), "r"(a[2]), "r"(a[3]), "r"(b[0]), "r"(b[1]));
}

// ---------------------------------------------------------------------------
// K1: per-(b,c) mean / rsqrt(var+eps)
// ---------------------------------------------------------------------------
__global__ void stats_kernel(const float* __restrict__ x) {
    int bc = blockIdx.x;
    const float4* xp = reinterpret_cast<const float4*>(x + (size_t)bc * HW);
    float s = 0.f, ss = 0.f;
    #pragma unroll 4
    for (int i = threadIdx.x; i < HW / 4; i += 256) {
        float4 v = xp[i];
        s  += (v.x + v.y) + (v.z + v.w);
        ss += v.x * v.x + v.y * v.y + v.z * v.z + v.w * v.w;
    }
    #pragma unroll
    for (int o = 16; o; o >>= 1) {
        s  += __shfl_down_sync(0xFFFFFFFFu, s, o);
        ss += __shfl_down_sync(0xFFFFFFFFu, ss, o);
    }
    __shared__ float sh_s[8], sh_ss[8];
    int wid = threadIdx.x >> 5, lid = threadIdx.x & 31;
    if (lid == 0) { sh_s[wid] = s; sh_ss[wid] = ss; }
    __syncthreads();
    if (threadIdx.x == 0) {
        float ts = 0.f, tss = 0.f;
        #pragma unroll
        for (int i = 0; i < 8; i++) { ts += sh_s[i]; tss += sh_ss[i]; }
        float m   = ts * (1.f / HW);
        float var = tss * (1.f / HW) - m * m;
        g_mean[bc] = m;
        g_rsig[bc] = rsqrtf(var + EPS);
    }
}

// ---------------------------------------------------------------------------
// Weight prepack: conv_w [OUT][C][3][3] fp32 -> [tap][oc][ci] bf16 hi/lo
// ---------------------------------------------------------------------------
__global__ void prepack_kernel(const float* __restrict__ cw) {
    int idx = blockIdx.x * 256 + threadIdx.x;
    int tap = idx >> 16;
    int r   = idx & 0xFFFF;
    int oc  = r >> 8, ci = r & 255;
    float v = cw[(oc * C + ci) * 9 + tap];
    __nv_bfloat16 h = __float2bfloat16(v);
    g_whi[idx] = h;
    g_wlo[idx] = __float2bfloat16(v - __bfloat162float(h));
}

// ---------------------------------------------------------------------------
// K2: normalize + adaptive grouped 3x3 + 1x1 + bias -> bf16 hi/lo NHWC padded
// ---------------------------------------------------------------------------
constexpr int T2W = 32, T2H = 16;

__global__ void ada_kernel(const float* __restrict__ x,
                           const float* __restrict__ ws,
                           const float* __restrict__ wp,
                           const float* __restrict__ bias) {
    __shared__ float s_in[CPG][T2H + 2][35];
    __shared__ float s_weff[CPG][CPG][9];
    __shared__ float s_wp[CPG][CPG];

    int bg = blockIdx.z;
    int b = bg / G, g = bg % G;
    int x0 = blockIdx.x * T2W, y0 = blockIdx.y * T2H;
    int tid = threadIdx.x;

    if (tid < CPG * CPG) {
        int o = tid >> 3, i = tid & 7;
        s_wp[o][i] = wp[(b * C + g * CPG + o) * CPG + i];
    }
    __syncthreads();

    for (int t = tid; t < CPG * CPG * 9; t += 256) {
        int o = t / 72, r = t % 72, j = r / 9, k = r % 9;
        float acc = 0.f;
        #pragma unroll
        for (int i = 0; i < CPG; i++)
            acc += s_wp[o][i] * ws[((b * C + g * CPG + i) * CPG + j) * 9 + k];
        s_weff[o][j][k] = acc;
    }

    for (int e = tid; e < CPG * (T2H + 2) * 34; e += 256) {
        int j   = e / ((T2H + 2) * 34);
        int r   = (e / 34) % (T2H + 2);
        int col = e % 34;
        int gy = reflect_idx(y0 + r - 1, H);
        int gx = reflect_idx(x0 + col - 1, W);
        int cg = b * C + g * CPG + j;
        s_in[j][r][col] = (x[(size_t)cg * HW + gy * W + gx] - g_mean[cg]) * g_rsig[cg];
    }
    __syncthreads();

    int px = (tid & 15) * 2;
    int py = tid >> 4;
    float acc[CPG][2];
    #pragma unroll
    for (int o = 0; o < CPG; o++) { acc[o][0] = 0.f; acc[o][1] = 0.f; }

    #pragma unroll
    for (int j = 0; j < CPG; j++) {
        #pragma unroll
        for (int ky = 0; ky < 3; ky++) {
            float i0 = s_in[j][py + ky][px + 0];
            float i1 = s_in[j][py + ky][px + 1];
            float i2 = s_in[j][py + ky][px + 2];
            float i3 = s_in[j][py + ky][px + 3];
            #pragma unroll
            for (int o = 0; o < CPG; o++) {
                float w0 = s_weff[o][j][ky * 3 + 0];
                float w1 = s_weff[o][j][ky * 3 + 1];
                float w2 = s_weff[o][j][ky * 3 + 2];
                acc[o][0] += w0 * i0 + w1 * i1 + w2 * i2;
                acc[o][1] += w0 * i1 + w1 * i2 + w2 * i3;
            }
        }
    }

    union U16 { __nv_bfloat16 h[8]; uint4 u; };
    U16 uh0, ul0, uh1, ul1;
    #pragma unroll
    for (int o = 0; o < CPG; o++) {
        float bz = bias[b * C + g * CPG + o];
        float v0 = acc[o][0] + bz;
        float v1 = acc[o][1] + bz;
        __nv_bfloat16 h0 = __float2bfloat16(v0);
        __nv_bfloat16 h1 = __float2bfloat16(v1);
        uh0.h[o] = h0; ul0.h[o] = __float2bfloat16(v0 - __bfloat162float(h0));
        uh1.h[o] = h1; ul1.h[o] = __float2bfloat16(v1 - __bfloat162float(h1));
    }
    size_t pbase = ((size_t)(b * HP + (y0 + py + 1)) * WP + (x0 + px + 1)) * C + g * CPG;
    *reinterpret_cast<uint4*>(g_yhi + pbase)     = uh0.u;
    *reinterpret_cast<uint4*>(g_ylo + pbase)     = ul0.u;
    *reinterpret_cast<uint4*>(g_yhi + pbase + C) = uh1.u;
    *reinterpret_cast<uint4*>(g_ylo + pbase + C) = ul1.u;
}

// ---------------------------------------------------------------------------
// Halo fill (reflect) for the padded NHWC planes
// ---------------------------------------------------------------------------
__global__ void halo_kernel() {
    int e = blockIdx.x;      // 0..515
    int b = blockIdx.y;
    int py, px;
    if (e < 130)       { py = 0;            px = e; }
    else if (e < 260)  { py = 129;          px = e - 130; }
    else if (e < 388)  { py = e - 260 + 1;  px = 0; }
    else               { py = e - 388 + 1;  px = 129; }
    int sy = reflect_idx(py - 1, H) + 1;
    int sx = reflect_idx(px - 1, W) + 1;
    size_t dst = ((size_t)(b * HP + py) * WP + px) * C + threadIdx.x;
    size_t src = ((size_t)(b * HP + sy) * WP + sx) * C + threadIdx.x;
    g_yhi[dst] = g_yhi[src];
    g_ylo[dst] = g_ylo[src];
}

// ---------------------------------------------------------------------------
// K3: mma.sync implicit-GEMM final conv, cp.async pipelined.
// CTA: 128 oc x 128 px (one row). 8 warps (2M x 4N), warp tile 64x32.
// Smem: A double buffer (hi+lo, 2x32KB) + B single (hi+lo, 33KB).
// Iteration = one (ci-chunk, tap). B reloaded only when dy changes (12x).
// ---------------------------------------------------------------------------
constexpr int A_BUF   = 32768;                     // one A buffer (hi+lo)
constexpr int OFF_A   = 0;                         // 2 buffers: 65536
constexpr int A_LO    = 16384;                     // lo-plane offset in a buffer
constexpr int OFF_B_HI = 65536;
constexpr int OFF_B_LO = OFF_B_HI + 130 * 128;     // 82176
constexpr int SMEM_K3  = OFF_B_LO + 130 * 128;     // 98816

__global__ __launch_bounds__(256, 2)
void final_mma_kernel(const float* __restrict__ cb, float* __restrict__ out) {
    extern __shared__ char sb[];
    uint32_t su = smem_u32(sb);
    int tid  = threadIdx.x;
    int warp = tid >> 5, lane = tid & 31;
    int wm = warp >> 2;          // 0..1  -> oc base wm*64
    int wn = warp & 3;           // 0..3  -> px base wn*32

    int y0  = blockIdx.x;        // output row
    int b   = blockIdx.y;
    int ocb = blockIdx.z;        // oc block of 128

    // per-thread staging slots (16B granularity)
    // A plane: 128 rows x 128B = 1024 chunks -> 4 per thread
    int a_r[4], a_j[4];
    uint32_t a_soff[4];
    #pragma unroll
    for (int q = 0; q < 4; q++) {
        int e = tid + q * 256;
        a_r[q] = e >> 3; a_j[q] = e & 7;
        a_soff[q] = SWZ128((uint32_t)(a_r[q] * 128 + a_j[q] * 16));
    }

    auto issue_A = [&](int tap, int c0, uint32_t abase) {
        #pragma unroll
        for (int q = 0; q < 4; q++) {
            size_t gi = ((size_t)(tap * OUT + ocb * MTILE + a_r[q])) * C
                        + c0 + a_j[q] * 8;
            cpa16(abase + a_soff[q], g_whi + gi);
            cpa16(abase + A_LO + a_soff[q], g_wlo + gi);
        }
    };
    auto issue_B = [&](int c0, int dyi) {
        for (int e = tid; e < 130 * 8; e += 256) {
            int r = e >> 3, j = e & 7;
            size_t gi = ((size_t)(b * HP + y0 + dyi) * WP + r) * C + c0 + j * 8;
            uint32_t off = SWZ128((uint32_t)(r * 128 + j * 16));
            cpa16(su + OFF_B_HI + off, g_yhi + gi);
            cpa16(su + OFF_B_LO + off, g_ylo + gi);
        }
    };

    float acc[4][4][4];
    #pragma unroll
    for (int mi = 0; mi < 4; mi++)
        #pragma unroll
        for (int ni = 0; ni < 4; ni++)
            #pragma unroll
            for (int q = 0; q < 4; q++)
                acc[mi][ni][q] = 0.f;

    // ldmatrix lane address components
    uint32_t a_row  = (uint32_t)(wm * 64 + (lane & 15));
    uint32_t a_kh   = (uint32_t)(lane >> 4) * 16;
    uint32_t b_row  = (uint32_t)(wn * 32 + (lane & 7) + ((lane >> 4) << 3));
    uint32_t b_kh   = (uint32_t)((lane >> 3) & 1) * 16;

    // prologue: B(c0=0, dy=0) + A(tap 0) into buffer 0
    issue_B(0, 0);
    issue_A(0, 0, su + OFF_A);
    CP_COMMIT();

    int cur = 0;
    for (int it = 0; it < 36; it++) {
        int c0  = (it / 9) * CCH;
        int tap = it % 9;
        int dxi = tap % 3;
        int nit = it + 1;
        int ntap = nit % 9;
        int nc0  = (nit / 9) * CCH;
        uint32_t abase_cur = su + OFF_A + cur * A_BUF;
        uint32_t abase_nxt = su + OFF_A + (cur ^ 1) * A_BUF;

        CP_WAIT0();
        __syncthreads();

        bool mid_prefetch = (nit < 36) && (ntap % 3 != 0);
        if (mid_prefetch) {               // B not touched -> overlap with compute
            issue_A(ntap, nc0, abase_nxt);
            CP_COMMIT();
        }

        // ---- compute current (A buffer cur, B, shift dxi)
        #pragma unroll
        for (int ks = 0; ks < 4; ks++) {
            uint32_t kb = (uint32_t)ks * 32;
            uint32_t aH[4][4], aL[4][4], bH[2][4], bL[2][4];
            #pragma unroll
            for (int mi = 0; mi < 4; mi++) {
                uint32_t off = SWZ128((a_row + mi * 16) * 128 + kb + a_kh);
                ldmx4(aH[mi], abase_cur + off);
                ldmx4(aL[mi], abase_cur + A_LO + off);
            }
            #pragma unroll
            for (int nh = 0; nh < 2; nh++) {
                uint32_t off = SWZ128((b_row + nh * 16 + dxi) * 128 + kb + b_kh);
                ldmx4(bH[nh], su + OFF_B_HI + off);
                ldmx4(bL[nh], su + OFF_B_LO + off);
            }
            #pragma unroll
            for (int mi = 0; mi < 4; mi++)
                #pragma unroll
                for (int ni = 0; ni < 4; ni++) {
                    const uint32_t* bh = &bH[ni >> 1][(ni & 1) * 2];
                    const uint32_t* bl = &bL[ni >> 1][(ni & 1) * 2];
                    mma16816(acc[mi][ni], aH[mi], bh);
                    mma16816(acc[mi][ni], aL[mi], bh);
                    mma16816(acc[mi][ni], aH[mi], bl);
                }
        }

        if (nit < 36 && !mid_prefetch) {  // next needs a new B row: sync, then load
            __syncthreads();
            issue_B(nc0, ntap / 3);
            issue_A(ntap, nc0, abase_nxt);
            CP_COMMIT();
        }
        cur ^= 1;
    }

    // Epilogue: +bias, direct float2 stores
    int row0 = lane >> 2;
    int col2 = (lane & 3) * 2;
    #pragma unroll
    for (int mi = 0; mi < 4; mi++) {
        int oc = ocb * MTILE + wm * 64 + mi * 16 + row0;
        float bz0 = cb[oc];
        float bz1 = cb[oc + 8];
        size_t base0 = (((size_t)(b * OUT + oc))     * H + y0) * W;
        size_t base1 = (((size_t)(b * OUT + oc + 8)) * H + y0) * W;
        #pragma unroll
        for (int ni = 0; ni < 4; ni++) {
            int px = wn * 32 + ni * 8 + col2;
            float2 v0 = { acc[mi][ni][0] + bz0, acc[mi][ni][1] + bz0 };
            float2 v1 = { acc[mi][ni][2] + bz1, acc[mi][ni][3] + bz1 };
            *reinterpret_cast<float2*>(out + base0 + px) = v0;
            *reinterpret_cast<float2*>(out + base1 + px) = v1;
        }
    }
}

// ---------------------------------------------------------------------------
extern "C" void kernel_launch(void* const* d_in, const int* in_sizes, int n_in,
                              void* d_out, int out_size) {
    const float* x    = (const float*)d_in[0];
    const float* ws   = (const float*)d_in[1];
    const float* wp   = (const float*)d_in[2];
    const float* bias = (const float*)d_in[3];
    const float* cw   = (const float*)d_in[4];
    const float* cb   = (const float*)d_in[5];
    float* out = (float*)d_out;

    cudaFuncSetAttribute(final_mma_kernel,
                         cudaFuncAttributeMaxDynamicSharedMemorySize, SMEM_K3);

    stats_kernel<<<B * C, 256>>>(x);
    prepack_kernel<<<9 * OUT * C / 256, 256>>>(cw);
    ada_kernel<<<dim3(W / T2W, H / T2H, B * G), 256>>>(x, ws, wp, bias);
    halo_kernel<<<dim3(516, B), 256>>>();
    final_mma_kernel<<<dim3(H, B, OUT / MTILE), 256, SMEM_K3>>>(cb, out);
}

// round 6
// speedup vs baseline: 4.1568x; 1.3189x over previous
#include <cuda_runtime.h>
#include <cuda_fp16.h>
#include <cstdint>

// ---------------------------------------------------------------------------
// AdaConv2d (sm_103, legacy mma.sync path):
//   K1 stats -> prepack (fp16 hi/lo weights) -> K2 instancenorm + adaptive
//   grouped conv (single fp16 y plane, NHWC reflect-pre-padded) -> halo ->
//   K3 fp16 2-term implicit-GEMM final 3x3 conv (A split hi/lo, B single).
// R6: 2 MMAs per k-step instead of 3 (fp16 precision budget), B double-buffered.
// ---------------------------------------------------------------------------

constexpr int B   = 8;
constexpr int C   = 256;
constexpr int H   = 128;
constexpr int W   = 128;
constexpr int G   = 32;
constexpr int CPG = 8;
constexpr int OUT = 256;
constexpr int HW  = H * W;
constexpr float EPS = 1e-5f;

constexpr int HP = H + 2;
constexpr int WP = W + 2;

constexpr int MTILE = 128;   // oc per CTA
constexpr int CCH   = 64;    // ci per smem stage

// Device scratch
static __device__ float g_mean[B * C];
static __device__ float g_rsig[B * C];
static __device__ __half g_yh[(size_t)B * HP * WP * C];   // NHWC padded, fp16
static __device__ __half g_whi[9 * OUT * C];              // [tap][oc][ci] fp16 hi
static __device__ __half g_wlo[9 * OUT * C];              // residual fp16 lo

__device__ __forceinline__ int reflect_idx(int v, int n) {
    v = v < 0 ? -v : v;
    v = v >= n ? 2 * n - 2 - v : v;
    return v;
}

#define SWZ128(off) ((off) ^ (((off) >> 3) & 0x70))

__device__ __forceinline__ uint32_t smem_u32(const void* p) {
    uint32_t a;
    asm("{ .reg .u64 t; cvta.to.shared.u64 t, %1; cvt.u32.u64 %0, t; }"
        : "=r"(a) : "l"(p));
    return a;
}
__device__ __forceinline__ void cpa16(uint32_t dst, const void* src) {
    asm volatile("cp.async.cg.shared.global [%0], [%1], 16;"
                 :: "r"(dst), "l"(src));
}
#define CP_COMMIT() asm volatile("cp.async.commit_group;" ::: "memory")
#define CP_WAIT0()  asm volatile("cp.async.wait_group 0;" ::: "memory")

__device__ __forceinline__ void ldmx4(uint32_t* r, uint32_t addr) {
    asm volatile("ldmatrix.sync.aligned.m8n8.x4.shared.b16 {%0,%1,%2,%3}, [%4];"
                 : "=r"(r[0]), "=r"(r[1]), "=r"(r[2]), "=r"(r[3]) : "r"(addr));
}
__device__ __forceinline__ void mma16816(float* d, const uint32_t* a,
                                         const uint32_t* b) {
    asm volatile(
        "mma.sync.aligned.m16n8k16.row.col.f32.f16.f16.f32 "
        "{%0,%1,%2,%3},{%4,%5,%6,%7},{%8,%9},{%0,%1,%2,%3};"
        : "+f"(d[0]), "+f"(d[1]), "+f"(d[2]), "+f"(d[3])
        : "r"(a[0]), "r"(a[1]), "r"(a[2]), "r"(a[3]), "r"(b[0]), "r"(b[1]));
}

// ---------------------------------------------------------------------------
// K1: per-(b,c) mean / rsqrt(var+eps)
// ---------------------------------------------------------------------------
__global__ void stats_kernel(const float* __restrict__ x) {
    int bc = blockIdx.x;
    const float4* xp = reinterpret_cast<const float4*>(x + (size_t)bc * HW);
    float s = 0.f, ss = 0.f;
    #pragma unroll 4
    for (int i = threadIdx.x; i < HW / 4; i += 256) {
        float4 v = xp[i];
        s  += (v.x + v.y) + (v.z + v.w);
        ss += v.x * v.x + v.y * v.y + v.z * v.z + v.w * v.w;
    }
    #pragma unroll
    for (int o = 16; o; o >>= 1) {
        s  += __shfl_down_sync(0xFFFFFFFFu, s, o);
        ss += __shfl_down_sync(0xFFFFFFFFu, ss, o);
    }
    __shared__ float sh_s[8], sh_ss[8];
    int wid = threadIdx.x >> 5, lid = threadIdx.x & 31;
    if (lid == 0) { sh_s[wid] = s; sh_ss[wid] = ss; }
    __syncthreads();
    if (threadIdx.x == 0) {
        float ts = 0.f, tss = 0.f;
        #pragma unroll
        for (int i = 0; i < 8; i++) { ts += sh_s[i]; tss += sh_ss[i]; }
        float m   = ts * (1.f / HW);
        float var = tss * (1.f / HW) - m * m;
        g_mean[bc] = m;
        g_rsig[bc] = rsqrtf(var + EPS);
    }
}

// ---------------------------------------------------------------------------
// Weight prepack: conv_w [OUT][C][3][3] fp32 -> [tap][oc][ci] fp16 hi/lo
// ---------------------------------------------------------------------------
__global__ void prepack_kernel(const float* __restrict__ cw) {
    int idx = blockIdx.x * 256 + threadIdx.x;
    int tap = idx >> 16;
    int r   = idx & 0xFFFF;
    int oc  = r >> 8, ci = r & 255;
    float v = cw[(oc * C + ci) * 9 + tap];
    __half h = __float2half_rn(v);
    g_whi[idx] = h;
    g_wlo[idx] = __float2half_rn(v - __half2float(h));
}

// ---------------------------------------------------------------------------
// K2: normalize + adaptive grouped 3x3 + 1x1 + bias -> fp16 NHWC padded
// ---------------------------------------------------------------------------
constexpr int T2W = 32, T2H = 16;

__global__ void ada_kernel(const float* __restrict__ x,
                           const float* __restrict__ ws,
                           const float* __restrict__ wp,
                           const float* __restrict__ bias) {
    __shared__ float s_in[CPG][T2H + 2][35];
    __shared__ float s_weff[CPG][CPG][9];
    __shared__ float s_wp[CPG][CPG];

    int bg = blockIdx.z;
    int b = bg / G, g = bg % G;
    int x0 = blockIdx.x * T2W, y0 = blockIdx.y * T2H;
    int tid = threadIdx.x;

    if (tid < CPG * CPG) {
        int o = tid >> 3, i = tid & 7;
        s_wp[o][i] = wp[(b * C + g * CPG + o) * CPG + i];
    }
    __syncthreads();

    for (int t = tid; t < CPG * CPG * 9; t += 256) {
        int o = t / 72, r = t % 72, j = r / 9, k = r % 9;
        float acc = 0.f;
        #pragma unroll
        for (int i = 0; i < CPG; i++)
            acc += s_wp[o][i] * ws[((b * C + g * CPG + i) * CPG + j) * 9 + k];
        s_weff[o][j][k] = acc;
    }

    for (int e = tid; e < CPG * (T2H + 2) * 34; e += 256) {
        int j   = e / ((T2H + 2) * 34);
        int r   = (e / 34) % (T2H + 2);
        int col = e % 34;
        int gy = reflect_idx(y0 + r - 1, H);
        int gx = reflect_idx(x0 + col - 1, W);
        int cg = b * C + g * CPG + j;
        s_in[j][r][col] = (x[(size_t)cg * HW + gy * W + gx] - g_mean[cg]) * g_rsig[cg];
    }
    __syncthreads();

    int px = (tid & 15) * 2;
    int py = tid >> 4;
    float acc[CPG][2];
    #pragma unroll
    for (int o = 0; o < CPG; o++) { acc[o][0] = 0.f; acc[o][1] = 0.f; }

    #pragma unroll
    for (int j = 0; j < CPG; j++) {
        #pragma unroll
        for (int ky = 0; ky < 3; ky++) {
            float i0 = s_in[j][py + ky][px + 0];
            float i1 = s_in[j][py + ky][px + 1];
            float i2 = s_in[j][py + ky][px + 2];
            float i3 = s_in[j][py + ky][px + 3];
            #pragma unroll
            for (int o = 0; o < CPG; o++) {
                float w0 = s_weff[o][j][ky * 3 + 0];
                float w1 = s_weff[o][j][ky * 3 + 1];
                float w2 = s_weff[o][j][ky * 3 + 2];
                acc[o][0] += w0 * i0 + w1 * i1 + w2 * i2;
                acc[o][1] += w0 * i1 + w1 * i2 + w2 * i3;
            }
        }
    }

    union U16 { __half h[8]; uint4 u; };
    U16 u0, u1;
    #pragma unroll
    for (int o = 0; o < CPG; o++) {
        float bz = bias[b * C + g * CPG + o];
        u0.h[o] = __float2half_rn(acc[o][0] + bz);
        u1.h[o] = __float2half_rn(acc[o][1] + bz);
    }
    size_t pbase = ((size_t)(b * HP + (y0 + py + 1)) * WP + (x0 + px + 1)) * C + g * CPG;
    *reinterpret_cast<uint4*>(g_yh + pbase)     = u0.u;
    *reinterpret_cast<uint4*>(g_yh + pbase + C) = u1.u;
}

// ---------------------------------------------------------------------------
// Halo fill (reflect) for the padded NHWC plane
// ---------------------------------------------------------------------------
__global__ void halo_kernel() {
    int e = blockIdx.x;      // 0..515
    int b = blockIdx.y;
    int py, px;
    if (e < 130)       { py = 0;            px = e; }
    else if (e < 260)  { py = 129;          px = e - 130; }
    else if (e < 388)  { py = e - 260 + 1;  px = 0; }
    else               { py = e - 388 + 1;  px = 129; }
    int sy = reflect_idx(py - 1, H) + 1;
    int sx = reflect_idx(px - 1, W) + 1;
    size_t dst = ((size_t)(b * HP + py) * WP + px) * C + threadIdx.x;
    size_t src = ((size_t)(b * HP + sy) * WP + sx) * C + threadIdx.x;
    g_yh[dst] = g_yh[src];
}

// ---------------------------------------------------------------------------
// K3: fp16 2-term implicit-GEMM final conv, cp.async pipelined.
// CTA: 128 oc x 128 px (one row). 8 warps (2M x 4N), warp tile 64x32.
// Smem: A double buffer (hi+lo, 2x32KB) + B double buffer (2x16.6KB).
// Iteration = one (ci-chunk, tap); group of 3 iters shares one B tile (dy).
// ---------------------------------------------------------------------------
constexpr int A_BUF  = 32768;                    // one A buffer (hi+lo)
constexpr int A_LO   = 16384;                    // lo-plane offset inside buffer
constexpr int OFF_A  = 0;                        // 2 buffers -> 65536
constexpr int B_BUF  = 130 * 128;                // 16640
constexpr int OFF_B  = 65536;                    // 2 buffers -> +33280
constexpr int SMEM_K3 = OFF_B + 2 * B_BUF;       // 98816

__global__ __launch_bounds__(256, 2)
void final_mma_kernel(const float* __restrict__ cb, float* __restrict__ out) {
    extern __shared__ char sb[];
    uint32_t su = smem_u32(sb);
    int tid  = threadIdx.x;
    int warp = tid >> 5, lane = tid & 31;
    int wm = warp >> 2;          // 0..1  -> oc base wm*64
    int wn = warp & 3;           // 0..3  -> px base wn*32

    int y0  = blockIdx.x;        // output row
    int b   = blockIdx.y;
    int ocb = blockIdx.z;        // oc block of 128

    // per-thread A staging slots (1024 16B chunks per plane -> 4/thread)
    int a_r[4], a_j[4];
    uint32_t a_soff[4];
    #pragma unroll
    for (int q = 0; q < 4; q++) {
        int e = tid + q * 256;
        a_r[q] = e >> 3; a_j[q] = e & 7;
        a_soff[q] = SWZ128((uint32_t)(a_r[q] * 128 + a_j[q] * 16));
    }

    auto issue_A = [&](int tap, int c0, uint32_t abase) {
        #pragma unroll
        for (int q = 0; q < 4; q++) {
            size_t gi = ((size_t)(tap * OUT + ocb * MTILE + a_r[q])) * C
                        + c0 + a_j[q] * 8;
            cpa16(abase + a_soff[q], g_whi + gi);
            cpa16(abase + A_LO + a_soff[q], g_wlo + gi);
        }
    };
    auto issue_B = [&](int c0, int dyi, uint32_t bbase) {
        for (int e = tid; e < 130 * 8; e += 256) {
            int r = e >> 3, j = e & 7;
            size_t gi = ((size_t)(b * HP + y0 + dyi) * WP + r) * C + c0 + j * 8;
            uint32_t off = SWZ128((uint32_t)(r * 128 + j * 16));
            cpa16(bbase + off, g_yh + gi);
        }
    };

    float acc[4][4][4];
    #pragma unroll
    for (int mi = 0; mi < 4; mi++)
        #pragma unroll
        for (int ni = 0; ni < 4; ni++)
            #pragma unroll
            for (int q = 0; q < 4; q++)
                acc[mi][ni][q] = 0.f;

    // ldmatrix lane address components
    uint32_t a_row = (uint32_t)(wm * 64 + (lane & 15));
    uint32_t a_kh  = (uint32_t)(lane >> 4) * 16;
    uint32_t b_row = (uint32_t)(wn * 32 + (lane & 7) + ((lane >> 4) << 3));
    uint32_t b_kh  = (uint32_t)((lane >> 3) & 1) * 16;

    // prologue: A(it=0) + B(group 0) into buffers 0
    issue_A(0, 0, su + OFF_A);
    issue_B(0, 0, su + OFF_B);
    CP_COMMIT();

    for (int it = 0; it < 36; it++) {
        int gi   = it / 3;             // (c0, dy) group: gi = c0i*3 + dyi
        int dxi  = it % 3;
        uint32_t abase = su + OFF_A + (it & 1) * A_BUF;
        uint32_t bbase = su + OFF_B + (gi & 1) * B_BUF;

        CP_WAIT0();
        __syncthreads();

        // prefetch next A every iter; next-group B at first iter of each group
        if (it + 1 < 36) {
            int nit = it + 1;
            issue_A(nit % 9, (nit / 9) * CCH, su + OFF_A + (nit & 1) * A_BUF);
        }
        if (dxi == 0 && gi + 1 < 12) {
            int ng = gi + 1;
            issue_B((ng / 3) * CCH, ng % 3, su + OFF_B + (ng & 1) * B_BUF);
        }
        CP_COMMIT();

        // ---- compute current (A buffer, B buffer, shift dxi)
        #pragma unroll
        for (int ks = 0; ks < 4; ks++) {
            uint32_t kb = (uint32_t)ks * 32;
            uint32_t aH[4][4], aL[4][4], bF[2][4];
            #pragma unroll
            for (int mi = 0; mi < 4; mi++) {
                uint32_t off = SWZ128((a_row + mi * 16) * 128 + kb + a_kh);
                ldmx4(aH[mi], abase + off);
                ldmx4(aL[mi], abase + A_LO + off);
            }
            #pragma unroll
            for (int nh = 0; nh < 2; nh++) {
                uint32_t off = SWZ128((b_row + nh * 16 + dxi) * 128 + kb + b_kh);
                ldmx4(bF[nh], bbase + off);
            }
            #pragma unroll
            for (int mi = 0; mi < 4; mi++)
                #pragma unroll
                for (int ni = 0; ni < 4; ni++) {
                    const uint32_t* bf = &bF[ni >> 1][(ni & 1) * 2];
                    mma16816(acc[mi][ni], aH[mi], bf);
                    mma16816(acc[mi][ni], aL[mi], bf);
                }
        }
    }

    // Epilogue: +bias, direct float2 stores
    int row0 = lane >> 2;
    int col2 = (lane & 3) * 2;
    #pragma unroll
    for (int mi = 0; mi < 4; mi++) {
        int oc = ocb * MTILE + wm * 64 + mi * 16 + row0;
        float bz0 = cb[oc];
        float bz1 = cb[oc + 8];
        size_t base0 = (((size_t)(b * OUT + oc))     * H + y0) * W;
        size_t base1 = (((size_t)(b * OUT + oc + 8)) * H + y0) * W;
        #pragma unroll
        for (int ni = 0; ni < 4; ni++) {
            int px = wn * 32 + ni * 8 + col2;
            float2 v0 = { acc[mi][ni][0] + bz0, acc[mi][ni][1] + bz0 };
            float2 v1 = { acc[mi][ni][2] + bz1, acc[mi][ni][3] + bz1 };
            *reinterpret_cast<float2*>(out + base0 + px) = v0;
            *reinterpret_cast<float2*>(out + base1 + px) = v1;
        }
    }
}

// ---------------------------------------------------------------------------
extern "C" void kernel_launch(void* const* d_in, const int* in_sizes, int n_in,
                              void* d_out, int out_size) {
    const float* x    = (const float*)d_in[0];
    const float* ws   = (const float*)d_in[1];
    const float* wp   = (const float*)d_in[2];
    const float* bias = (const float*)d_in[3];
    const float* cw   = (const float*)d_in[4];
    const float* cb   = (const float*)d_in[5];
    float* out = (float*)d_out;

    cudaFuncSetAttribute(final_mma_kernel,
                         cudaFuncAttributeMaxDynamicSharedMemorySize, SMEM_K3);

    stats_kernel<<<B * C, 256>>>(x);
    prepack_kernel<<<9 * OUT * C / 256, 256>>>(cw);
    ada_kernel<<<dim3(W / T2W, H / T2H, B * G), 256>>>(x, ws, wp, bias);
    halo_kernel<<<dim3(516, B), 256>>>();
    final_mma_kernel<<<dim3(H, B, OUT / MTILE), 256, SMEM_K3>>>(cb, out);
}

// round 7
// speedup vs baseline: 5.9358x; 1.4280x over previous
#include <cuda_runtime.h>
#include <cuda_fp16.h>
#include <cstdint>

// ---------------------------------------------------------------------------
// AdaConv2d (sm_103, legacy mma.sync path):
//   K1 stats -> prepack (single fp16 weights) -> K2 instancenorm + adaptive
//   grouped conv (single fp16 y plane, NHWC reflect-pre-padded) -> halo ->
//   K3 fp16 single-term implicit-GEMM final 3x3 conv.
// R7: 1 MMA per k-step (was 2). Error budget: A+B fp16 rounding ~2.8e-4 < 1e-3.
// ---------------------------------------------------------------------------

constexpr int B   = 8;
constexpr int C   = 256;
constexpr int H   = 128;
constexpr int W   = 128;
constexpr int G   = 32;
constexpr int CPG = 8;
constexpr int OUT = 256;
constexpr int HW  = H * W;
constexpr float EPS = 1e-5f;

constexpr int HP = H + 2;
constexpr int WP = W + 2;

constexpr int MTILE = 128;   // oc per CTA
constexpr int CCH   = 64;    // ci per smem stage

// Device scratch
static __device__ float g_mean[B * C];
static __device__ float g_rsig[B * C];
static __device__ __half g_yh[(size_t)B * HP * WP * C];   // NHWC padded, fp16
static __device__ __half g_wh[9 * OUT * C];               // [tap][oc][ci] fp16

__device__ __forceinline__ int reflect_idx(int v, int n) {
    v = v < 0 ? -v : v;
    v = v >= n ? 2 * n - 2 - v : v;
    return v;
}

#define SWZ128(off) ((off) ^ (((off) >> 3) & 0x70))

__device__ __forceinline__ uint32_t smem_u32(const void* p) {
    uint32_t a;
    asm("{ .reg .u64 t; cvta.to.shared.u64 t, %1; cvt.u32.u64 %0, t; }"
        : "=r"(a) : "l"(p));
    return a;
}
__device__ __forceinline__ void cpa16(uint32_t dst, const void* src) {
    asm volatile("cp.async.cg.shared.global [%0], [%1], 16;"
                 :: "r"(dst), "l"(src));
}
#define CP_COMMIT() asm volatile("cp.async.commit_group;" ::: "memory")
#define CP_WAIT0()  asm volatile("cp.async.wait_group 0;" ::: "memory")

__device__ __forceinline__ void ldmx4(uint32_t* r, uint32_t addr) {
    asm volatile("ldmatrix.sync.aligned.m8n8.x4.shared.b16 {%0,%1,%2,%3}, [%4];"
                 : "=r"(r[0]), "=r"(r[1]), "=r"(r[2]), "=r"(r[3]) : "r"(addr));
}
__device__ __forceinline__ void mma16816(float* d, const uint32_t* a,
                                         const uint32_t* b) {
    asm volatile(
        "mma.sync.aligned.m16n8k16.row.col.f32.f16.f16.f32 "
        "{%0,%1,%2,%3},{%4,%5,%6,%7},{%8,%9},{%0,%1,%2,%3};"
        : "+f"(d[0]), "+f"(d[1]), "+f"(d[2]), "+f"(d[3])
        : "r"(a[0]), "r"(a[1]), "r"(a[2]), "r"(a[3]), "r"(b[0]), "r"(b[1]));
}

// ---------------------------------------------------------------------------
// K1: per-(b,c) mean / rsqrt(var+eps)
// ---------------------------------------------------------------------------
__global__ void stats_kernel(const float* __restrict__ x) {
    int bc = blockIdx.x;
    const float4* xp = reinterpret_cast<const float4*>(x + (size_t)bc * HW);
    float s = 0.f, ss = 0.f;
    #pragma unroll 4
    for (int i = threadIdx.x; i < HW / 4; i += 256) {
        float4 v = xp[i];
        s  += (v.x + v.y) + (v.z + v.w);
        ss += v.x * v.x + v.y * v.y + v.z * v.z + v.w * v.w;
    }
    #pragma unroll
    for (int o = 16; o; o >>= 1) {
        s  += __shfl_down_sync(0xFFFFFFFFu, s, o);
        ss += __shfl_down_sync(0xFFFFFFFFu, ss, o);
    }
    __shared__ float sh_s[8], sh_ss[8];
    int wid = threadIdx.x >> 5, lid = threadIdx.x & 31;
    if (lid == 0) { sh_s[wid] = s; sh_ss[wid] = ss; }
    __syncthreads();
    if (threadIdx.x == 0) {
        float ts = 0.f, tss = 0.f;
        #pragma unroll
        for (int i = 0; i < 8; i++) { ts += sh_s[i]; tss += sh_ss[i]; }
        float m   = ts * (1.f / HW);
        float var = tss * (1.f / HW) - m * m;
        g_mean[bc] = m;
        g_rsig[bc] = rsqrtf(var + EPS);
    }
}

// ---------------------------------------------------------------------------
// Weight prepack: conv_w [OUT][C][3][3] fp32 -> [tap][oc][ci] fp16
// ---------------------------------------------------------------------------
__global__ void prepack_kernel(const float* __restrict__ cw) {
    int idx = blockIdx.x * 256 + threadIdx.x;
    int tap = idx >> 16;
    int r   = idx & 0xFFFF;
    int oc  = r >> 8, ci = r & 255;
    g_wh[idx] = __float2half_rn(cw[(oc * C + ci) * 9 + tap]);
}

// ---------------------------------------------------------------------------
// K2: normalize + adaptive grouped 3x3 + 1x1 + bias -> fp16 NHWC padded
// ---------------------------------------------------------------------------
constexpr int T2W = 32, T2H = 16;

__global__ void ada_kernel(const float* __restrict__ x,
                           const float* __restrict__ ws,
                           const float* __restrict__ wp,
                           const float* __restrict__ bias) {
    __shared__ float s_in[CPG][T2H + 2][35];
    __shared__ float s_weff[CPG][CPG][9];
    __shared__ float s_wp[CPG][CPG];

    int bg = blockIdx.z;
    int b = bg / G, g = bg % G;
    int x0 = blockIdx.x * T2W, y0 = blockIdx.y * T2H;
    int tid = threadIdx.x;

    if (tid < CPG * CPG) {
        int o = tid >> 3, i = tid & 7;
        s_wp[o][i] = wp[(b * C + g * CPG + o) * CPG + i];
    }
    __syncthreads();

    for (int t = tid; t < CPG * CPG * 9; t += 256) {
        int o = t / 72, r = t % 72, j = r / 9, k = r % 9;
        float acc = 0.f;
        #pragma unroll
        for (int i = 0; i < CPG; i++)
            acc += s_wp[o][i] * ws[((b * C + g * CPG + i) * CPG + j) * 9 + k];
        s_weff[o][j][k] = acc;
    }

    for (int e = tid; e < CPG * (T2H + 2) * 34; e += 256) {
        int j   = e / ((T2H + 2) * 34);
        int r   = (e / 34) % (T2H + 2);
        int col = e % 34;
        int gy = reflect_idx(y0 + r - 1, H);
        int gx = reflect_idx(x0 + col - 1, W);
        int cg = b * C + g * CPG + j;
        s_in[j][r][col] = (x[(size_t)cg * HW + gy * W + gx] - g_mean[cg]) * g_rsig[cg];
    }
    __syncthreads();

    int px = (tid & 15) * 2;
    int py = tid >> 4;
    float acc[CPG][2];
    #pragma unroll
    for (int o = 0; o < CPG; o++) { acc[o][0] = 0.f; acc[o][1] = 0.f; }

    #pragma unroll
    for (int j = 0; j < CPG; j++) {
        #pragma unroll
        for (int ky = 0; ky < 3; ky++) {
            float i0 = s_in[j][py + ky][px + 0];
            float i1 = s_in[j][py + ky][px + 1];
            float i2 = s_in[j][py + ky][px + 2];
            float i3 = s_in[j][py + ky][px + 3];
            #pragma unroll
            for (int o = 0; o < CPG; o++) {
                float w0 = s_weff[o][j][ky * 3 + 0];
                float w1 = s_weff[o][j][ky * 3 + 1];
                float w2 = s_weff[o][j][ky * 3 + 2];
                acc[o][0] += w0 * i0 + w1 * i1 + w2 * i2;
                acc[o][1] += w0 * i1 + w1 * i2 + w2 * i3;
            }
        }
    }

    union U16 { __half h[8]; uint4 u; };
    U16 u0, u1;
    #pragma unroll
    for (int o = 0; o < CPG; o++) {
        float bz = bias[b * C + g * CPG + o];
        u0.h[o] = __float2half_rn(acc[o][0] + bz);
        u1.h[o] = __float2half_rn(acc[o][1] + bz);
    }
    size_t pbase = ((size_t)(b * HP + (y0 + py + 1)) * WP + (x0 + px + 1)) * C + g * CPG;
    *reinterpret_cast<uint4*>(g_yh + pbase)     = u0.u;
    *reinterpret_cast<uint4*>(g_yh + pbase + C) = u1.u;
}

// ---------------------------------------------------------------------------
// Halo fill (reflect) for the padded NHWC plane
// ---------------------------------------------------------------------------
__global__ void halo_kernel() {
    int e = blockIdx.x;      // 0..515
    int b = blockIdx.y;
    int py, px;
    if (e < 130)       { py = 0;            px = e; }
    else if (e < 260)  { py = 129;          px = e - 130; }
    else if (e < 388)  { py = e - 260 + 1;  px = 0; }
    else               { py = e - 388 + 1;  px = 129; }
    int sy = reflect_idx(py - 1, H) + 1;
    int sx = reflect_idx(px - 1, W) + 1;
    size_t dst = ((size_t)(b * HP + py) * WP + px) * C + threadIdx.x;
    size_t src = ((size_t)(b * HP + sy) * WP + sx) * C + threadIdx.x;
    g_yh[dst] = g_yh[src];
}

// ---------------------------------------------------------------------------
// K3: fp16 single-term implicit-GEMM final conv, cp.async pipelined.
// CTA: 128 oc x 128 px (one row). 8 warps (2M x 4N), warp tile 64x32.
// Smem: A double buffer (2x16KB) + B double buffer (2x16.6KB).
// Iteration = one (ci-chunk, tap); group of 3 iters shares one B tile (dy).
// ---------------------------------------------------------------------------
constexpr int A_BUF  = 16384;                    // one A buffer
constexpr int OFF_A  = 0;                        // 2 buffers -> 32768
constexpr int B_BUF  = 130 * 128;                // 16640
constexpr int OFF_B  = 32768;                    // 2 buffers -> +33280
constexpr int SMEM_K3 = OFF_B + 2 * B_BUF;       // 66048

__global__ __launch_bounds__(256, 2)
void final_mma_kernel(const float* __restrict__ cb, float* __restrict__ out) {
    extern __shared__ char sb[];
    uint32_t su = smem_u32(sb);
    int tid  = threadIdx.x;
    int warp = tid >> 5, lane = tid & 31;
    int wm = warp >> 2;          // 0..1  -> oc base wm*64
    int wn = warp & 3;           // 0..3  -> px base wn*32

    int y0  = blockIdx.x;        // output row
    int b   = blockIdx.y;
    int ocb = blockIdx.z;        // oc block of 128

    // per-thread A staging slots (1024 16B chunks -> 4/thread)
    int a_r[4], a_j[4];
    uint32_t a_soff[4];
    #pragma unroll
    for (int q = 0; q < 4; q++) {
        int e = tid + q * 256;
        a_r[q] = e >> 3; a_j[q] = e & 7;
        a_soff[q] = SWZ128((uint32_t)(a_r[q] * 128 + a_j[q] * 16));
    }

    auto issue_A = [&](int tap, int c0, uint32_t abase) {
        #pragma unroll
        for (int q = 0; q < 4; q++) {
            size_t gi = ((size_t)(tap * OUT + ocb * MTILE + a_r[q])) * C
                        + c0 + a_j[q] * 8;
            cpa16(abase + a_soff[q], g_wh + gi);
        }
    };
    auto issue_B = [&](int c0, int dyi, uint32_t bbase) {
        for (int e = tid; e < 130 * 8; e += 256) {
            int r = e >> 3, j = e & 7;
            size_t gi = ((size_t)(b * HP + y0 + dyi) * WP + r) * C + c0 + j * 8;
            uint32_t off = SWZ128((uint32_t)(r * 128 + j * 16));
            cpa16(bbase + off, g_yh + gi);
        }
    };

    float acc[4][4][4];
    #pragma unroll
    for (int mi = 0; mi < 4; mi++)
        #pragma unroll
        for (int ni = 0; ni < 4; ni++)
            #pragma unroll
            for (int q = 0; q < 4; q++)
                acc[mi][ni][q] = 0.f;

    // ldmatrix lane address components
    uint32_t a_row = (uint32_t)(wm * 64 + (lane & 15));
    uint32_t a_kh  = (uint32_t)(lane >> 4) * 16;
    uint32_t b_row = (uint32_t)(wn * 32 + (lane & 7) + ((lane >> 4) << 3));
    uint32_t b_kh  = (uint32_t)((lane >> 3) & 1) * 16;

    // prologue: A(it=0) + B(group 0) into buffers 0
    issue_A(0, 0, su + OFF_A);
    issue_B(0, 0, su + OFF_B);
    CP_COMMIT();

    for (int it = 0; it < 36; it++) {
        int gi   = it / 3;             // (c0, dy) group
        int dxi  = it % 3;
        uint32_t abase = su + OFF_A + (it & 1) * A_BUF;
        uint32_t bbase = su + OFF_B + (gi & 1) * B_BUF;

        CP_WAIT0();
        __syncthreads();

        // prefetch next A every iter; next-group B at first iter of each group
        if (it + 1 < 36) {
            int nit = it + 1;
            issue_A(nit % 9, (nit / 9) * CCH, su + OFF_A + (nit & 1) * A_BUF);
        }
        if (dxi == 0 && gi + 1 < 12) {
            int ng = gi + 1;
            issue_B((ng / 3) * CCH, ng % 3, su + OFF_B + (ng & 1) * B_BUF);
        }
        CP_COMMIT();

        // ---- compute current (A buffer, B buffer, shift dxi)
        #pragma unroll
        for (int ks = 0; ks < 4; ks++) {
            uint32_t kb = (uint32_t)ks * 32;
            uint32_t aF[4][4], bF[2][4];
            #pragma unroll
            for (int mi = 0; mi < 4; mi++) {
                uint32_t off = SWZ128((a_row + mi * 16) * 128 + kb + a_kh);
                ldmx4(aF[mi], abase + off);
            }
            #pragma unroll
            for (int nh = 0; nh < 2; nh++) {
                uint32_t off = SWZ128((b_row + nh * 16 + dxi) * 128 + kb + b_kh);
                ldmx4(bF[nh], bbase + off);
            }
            #pragma unroll
            for (int mi = 0; mi < 4; mi++)
                #pragma unroll
                for (int ni = 0; ni < 4; ni++)
                    mma16816(acc[mi][ni], aF[mi], &bF[ni >> 1][(ni & 1) * 2]);
        }
    }

    // Epilogue: +bias, direct float2 stores
    int row0 = lane >> 2;
    int col2 = (lane & 3) * 2;
    #pragma unroll
    for (int mi = 0; mi < 4; mi++) {
        int oc = ocb * MTILE + wm * 64 + mi * 16 + row0;
        float bz0 = cb[oc];
        float bz1 = cb[oc + 8];
        size_t base0 = (((size_t)(b * OUT + oc))     * H + y0) * W;
        size_t base1 = (((size_t)(b * OUT + oc + 8)) * H + y0) * W;
        #pragma unroll
        for (int ni = 0; ni < 4; ni++) {
            int px = wn * 32 + ni * 8 + col2;
            float2 v0 = { acc[mi][ni][0] + bz0, acc[mi][ni][1] + bz0 };
            float2 v1 = { acc[mi][ni][2] + bz1, acc[mi][ni][3] + bz1 };
            *reinterpret_cast<float2*>(out + base0 + px) = v0;
            *reinterpret_cast<float2*>(out + base1 + px) = v1;
        }
    }
}

// ---------------------------------------------------------------------------
extern "C" void kernel_launch(void* const* d_in, const int* in_sizes, int n_in,
                              void* d_out, int out_size) {
    const float* x    = (const float*)d_in[0];
    const float* ws   = (const float*)d_in[1];
    const float* wp   = (const float*)d_in[2];
    const float* bias = (const float*)d_in[3];
    const float* cw   = (const float*)d_in[4];
    const float* cb   = (const float*)d_in[5];
    float* out = (float*)d_out;

    cudaFuncSetAttribute(final_mma_kernel,
                         cudaFuncAttributeMaxDynamicSharedMemorySize, SMEM_K3);

    stats_kernel<<<B * C, 256>>>(x);
    prepack_kernel<<<9 * OUT * C / 256, 256>>>(cw);
    ada_kernel<<<dim3(W / T2W, H / T2H, B * G), 256>>>(x, ws, wp, bias);
    halo_kernel<<<dim3(516, B), 256>>>();
    final_mma_kernel<<<dim3(H, B, OUT / MTILE), 256, SMEM_K3>>>(cb, out);
}